// round 3
// baseline (speedup 1.0000x reference)
#include <cuda_runtime.h>

// ---------------------------------------------------------------------------
// Problem constants
// ---------------------------------------------------------------------------
#define Bc 4
#define Tc 2048
#define Kc 512
#define Hc 8
#define KH (Kc * Hc)       // 4096
#define M0 (Bc * Tc)       // 8192
#define INV4 0.2102241038134287f   // 512^(-0.25)

// GEMM tiling
#define BM 128
#define BN 128
#define BKD 16
#define TM 8
#define TN 8
#define NTHREADS 256

// ---------------------------------------------------------------------------
// Static device scratch (allocation-free; module-load allocated)
// ---------------------------------------------------------------------------
__device__ float g_q  [(size_t)Bc * Hc * Tc * Kc];   // [b,h,t,k]  (pre-scaled)
__device__ float g_kT [(size_t)Bc * Hc * Kc * Tc];   // [b,h,k,t]  (pre-scaled, transposed)
__device__ float g_v  [(size_t)Bc * Hc * Tc * Kc];   // [b,h,t,k]
__device__ float g_s  [(size_t)Bc * Hc * Tc * Tc];   // scores / probs [b,h,q,s]
__device__ float g_att[(size_t)Bc * Tc * KH];        // [b,t,h*k]

// ---------------------------------------------------------------------------
// Core 128x128 SGEMM tile: C_tile = A[blockM:+128, :Kdim] * B[:Kdim, blockN:+128]
// A row-major (lda), B row-major (ldb). All dims multiples of tile sizes.
// ---------------------------------------------------------------------------
__device__ __forceinline__ void gemm_tile(
    const float* __restrict__ A, int lda,
    const float* __restrict__ Bmat, int ldb,
    int Kdim, int blockM, int blockN,
    float acc[TM][TN])
{
    __shared__ float As[BKD][BM];   // k-major for conflict-free frag loads
    __shared__ float Bs[BKD][BN];

    const int tid = threadIdx.x;
    const int tx = tid & 15;        // N direction (16)
    const int ty = tid >> 4;        // M direction (16)

    const int a_row = tid >> 2;         // 0..63
    const int a_col = (tid & 3) << 2;   // 0,4,8,12
    const int b_row = tid >> 5;         // 0..7
    const int b_col = (tid & 31) << 2;  // 0..124

#pragma unroll
    for (int i = 0; i < TM; i++)
#pragma unroll
        for (int j = 0; j < TN; j++) acc[i][j] = 0.f;

    const float* Aptr = A + (size_t)blockM * lda;
    const float* Bptr = Bmat + blockN;

    for (int k0 = 0; k0 < Kdim; k0 += BKD) {
        // Load A tile (128 x 16), store transposed into As
#pragma unroll
        for (int i = 0; i < 2; i++) {
            const int r = a_row + i * 64;
            const float4 va = *(const float4*)(Aptr + (size_t)r * lda + k0 + a_col);
            As[a_col + 0][r] = va.x;
            As[a_col + 1][r] = va.y;
            As[a_col + 2][r] = va.z;
            As[a_col + 3][r] = va.w;
        }
        // Load B tile (16 x 128)
#pragma unroll
        for (int i = 0; i < 2; i++) {
            const int r = b_row + i * 8;
            *(float4*)&Bs[r][b_col] =
                *(const float4*)(Bptr + (size_t)(k0 + r) * ldb + b_col);
        }
        __syncthreads();

#pragma unroll
        for (int kk = 0; kk < BKD; kk++) {
            float a[TM], b[TN];
            *(float4*)&a[0] = *(const float4*)&As[kk][ty * TM];
            *(float4*)&a[4] = *(const float4*)&As[kk][ty * TM + 4];
            *(float4*)&b[0] = *(const float4*)&Bs[kk][tx * TN];
            *(float4*)&b[4] = *(const float4*)&Bs[kk][tx * TN + 4];
#pragma unroll
            for (int i = 0; i < TM; i++)
#pragma unroll
                for (int j = 0; j < TN; j++)
                    acc[i][j] = fmaf(a[i], b[j], acc[i][j]);
        }
        __syncthreads();
    }
}

// ---------------------------------------------------------------------------
// Stage 1: fused QKV projection. grid.z: 0=Q, 1=K(transposed store), 2=V
// x: [8192, 512], W: [512, 4096]
// ---------------------------------------------------------------------------
__global__ __launch_bounds__(NTHREADS, 2)
void qkv_kernel(const float* __restrict__ x,
                const float* __restrict__ Wq,
                const float* __restrict__ Wk,
                const float* __restrict__ Wv)
{
    const int mode = blockIdx.z;
    const float* W = (mode == 0) ? Wq : (mode == 1) ? Wk : Wv;
    const int blockM = blockIdx.y * BM;
    const int blockN = blockIdx.x * BN;

    float acc[TM][TN];
    gemm_tile(x, Kc, W, KH, Kc, blockM, blockN, acc);

    const int tx = threadIdx.x & 15, ty = threadIdx.x >> 4;
    const int m0 = blockM + ty * TM;   // 8 consecutive (b,t) rows, same b
    const int n0 = blockN + tx * TN;   // 8 consecutive cols, same head
    const int b  = m0 >> 11;
    const int t0 = m0 & (Tc - 1);
    const int h  = n0 >> 9;
    const int k0n = n0 & (Kc - 1);

    if (mode == 1) {
        // K stored transposed [b,h,k,t], scaled
        float* base = g_kT + (size_t)(b * Hc + h) * Kc * Tc;
#pragma unroll
        for (int j = 0; j < TN; j++) {
            float* pp = base + (size_t)(k0n + j) * Tc + t0;
            *(float4*)pp =
                make_float4(acc[0][j] * INV4, acc[1][j] * INV4,
                            acc[2][j] * INV4, acc[3][j] * INV4);
            *(float4*)(pp + 4) =
                make_float4(acc[4][j] * INV4, acc[5][j] * INV4,
                            acc[6][j] * INV4, acc[7][j] * INV4);
        }
    } else {
        float* dst = (mode == 0) ? g_q : g_v;
        const float sc = (mode == 0) ? INV4 : 1.f;
        float* base = dst + ((size_t)(b * Hc + h) * Tc + t0) * Kc + k0n;
#pragma unroll
        for (int i = 0; i < TM; i++) {
            *(float4*)(base + (size_t)i * Kc) =
                make_float4(acc[i][0] * sc, acc[i][1] * sc,
                            acc[i][2] * sc, acc[i][3] * sc);
            *(float4*)(base + (size_t)i * Kc + 4) =
                make_float4(acc[i][4] * sc, acc[i][5] * sc,
                            acc[i][6] * sc, acc[i][7] * sc);
        }
    }
}

// ---------------------------------------------------------------------------
// Stage 2: scores S = Q * K^T per (b,h). NN GEMM thanks to transposed K store.
// ---------------------------------------------------------------------------
__global__ __launch_bounds__(NTHREADS, 2)
void scores_kernel()
{
    const int bh = blockIdx.z;
    const float* Aq = g_q  + (size_t)bh * Tc * Kc;
    const float* Bk = g_kT + (size_t)bh * Kc * Tc;
    float*       Cs = g_s  + (size_t)bh * Tc * Tc;
    const int blockM = blockIdx.y * BM;
    const int blockN = blockIdx.x * BN;

    float acc[TM][TN];
    gemm_tile(Aq, Kc, Bk, Tc, Kc, blockM, blockN, acc);

    const int tx = threadIdx.x & 15, ty = threadIdx.x >> 4;
    float* base = Cs + (size_t)(blockM + ty * TM) * Tc + blockN + tx * TN;
#pragma unroll
    for (int i = 0; i < TM; i++) {
        *(float4*)(base + (size_t)i * Tc) =
            make_float4(acc[i][0], acc[i][1], acc[i][2], acc[i][3]);
        *(float4*)(base + (size_t)i * Tc + 4) =
            make_float4(acc[i][4], acc[i][5], acc[i][6], acc[i][7]);
    }
}

// ---------------------------------------------------------------------------
// Stage 3: row softmax over s (row length 2048). One CTA per row,
// 8 elements per thread held in registers (single pass over memory).
// ---------------------------------------------------------------------------
__global__ void softmax_kernel()
{
    __shared__ float red[8];
    const size_t row = blockIdx.x;
    float* p = g_s + row * (size_t)Tc;
    const int tid = threadIdx.x;

    float v[8];
    *(float4*)&v[0] = *(const float4*)(p + tid * 8);
    *(float4*)&v[4] = *(const float4*)(p + tid * 8 + 4);

    float mx = v[0];
#pragma unroll
    for (int i = 1; i < 8; i++) mx = fmaxf(mx, v[i]);
#pragma unroll
    for (int o = 16; o > 0; o >>= 1)
        mx = fmaxf(mx, __shfl_xor_sync(0xffffffffu, mx, o));
    if ((tid & 31) == 0) red[tid >> 5] = mx;
    __syncthreads();
    mx = red[0];
#pragma unroll
    for (int i = 1; i < 8; i++) mx = fmaxf(mx, red[i]);

    float s = 0.f;
#pragma unroll
    for (int i = 0; i < 8; i++) { v[i] = __expf(v[i] - mx); s += v[i]; }
#pragma unroll
    for (int o = 16; o > 0; o >>= 1)
        s += __shfl_xor_sync(0xffffffffu, s, o);
    __syncthreads();                    // everyone done reading red (max)
    if ((tid & 31) == 0) red[tid >> 5] = s;
    __syncthreads();
    s = 0.f;
#pragma unroll
    for (int i = 0; i < 8; i++) s += red[i];
    const float inv = 1.f / s;
#pragma unroll
    for (int i = 0; i < 8; i++) v[i] *= inv;

    *(float4*)(p + tid * 8)     = *(const float4*)&v[0];
    *(float4*)(p + tid * 8 + 4) = *(const float4*)&v[4];
}

// ---------------------------------------------------------------------------
// Stage 4: out_h = P * V per (b,h); store into [b,t,h*k] layout.
// ---------------------------------------------------------------------------
__global__ __launch_bounds__(NTHREADS, 2)
void pv_kernel()
{
    const int bh = blockIdx.z;
    const int b = bh >> 3;
    const int h = bh & 7;
    const float* Ap = g_s + (size_t)bh * Tc * Tc;
    const float* Bv = g_v + (size_t)bh * Tc * Kc;
    const int blockM = blockIdx.y * BM;
    const int blockN = blockIdx.x * BN;

    float acc[TM][TN];
    gemm_tile(Ap, Tc, Bv, Kc, Tc, blockM, blockN, acc);

    const int tx = threadIdx.x & 15, ty = threadIdx.x >> 4;
    float* base = g_att + ((size_t)b * Tc + blockM + ty * TM) * KH
                        + h * Kc + blockN + tx * TN;
#pragma unroll
    for (int i = 0; i < TM; i++) {
        *(float4*)(base + (size_t)i * KH) =
            make_float4(acc[i][0], acc[i][1], acc[i][2], acc[i][3]);
        *(float4*)(base + (size_t)i * KH + 4) =
            make_float4(acc[i][4], acc[i][5], acc[i][6], acc[i][7]);
    }
}

// ---------------------------------------------------------------------------
// Stage 5: final projection + bias: out = att * Wu + bu. [8192,4096]x[4096,512]
// ---------------------------------------------------------------------------
__global__ __launch_bounds__(NTHREADS, 2)
void out_kernel(const float* __restrict__ Wu,
                const float* __restrict__ bu,
                float* __restrict__ out)
{
    const int blockM = blockIdx.y * BM;
    const int blockN = blockIdx.x * BN;

    float acc[TM][TN];
    gemm_tile(g_att, KH, Wu, Kc, KH, blockM, blockN, acc);

    const int tx = threadIdx.x & 15, ty = threadIdx.x >> 4;
    const int n0 = blockN + tx * TN;
    const float4 bias0 = *(const float4*)(bu + n0);
    const float4 bias1 = *(const float4*)(bu + n0 + 4);
    float* base = out + (size_t)(blockM + ty * TM) * Kc + n0;
#pragma unroll
    for (int i = 0; i < TM; i++) {
        *(float4*)(base + (size_t)i * Kc) =
            make_float4(acc[i][0] + bias0.x, acc[i][1] + bias0.y,
                        acc[i][2] + bias0.z, acc[i][3] + bias0.w);
        *(float4*)(base + (size_t)i * Kc + 4) =
            make_float4(acc[i][4] + bias1.x, acc[i][5] + bias1.y,
                        acc[i][6] + bias1.z, acc[i][7] + bias1.w);
    }
}

// ---------------------------------------------------------------------------
// kernel_launch
// Inputs (metadata order): x, Wq, Wk, Wv, Wu, bu. Output: float [8192, 512].
// ---------------------------------------------------------------------------
extern "C" void kernel_launch(void* const* d_in, const int* in_sizes, int n_in,
                              void* d_out, int out_size)
{
    const float* x  = (const float*)d_in[0];
    const float* Wq = (const float*)d_in[1];
    const float* Wk = (const float*)d_in[2];
    const float* Wv = (const float*)d_in[3];
    const float* Wu = (const float*)d_in[4];
    const float* bu = (const float*)d_in[5];
    float* out = (float*)d_out;

    (void)in_sizes; (void)n_in; (void)out_size;

    dim3 blk(NTHREADS);

    // Stage 1: QKV projections (8192 x 4096 x 512, x3)
    qkv_kernel<<<dim3(KH / BN, M0 / BM, 3), blk>>>(x, Wq, Wk, Wv);

    // Stage 2: scores (2048 x 2048 x 512, x32 batches)
    scores_kernel<<<dim3(Tc / BN, Tc / BM, Bc * Hc), blk>>>();

    // Stage 3: softmax over 65536 rows of 2048
    softmax_kernel<<<Bc * Hc * Tc, 256>>>();

    // Stage 4: PV (2048 x 512 x 2048, x32 batches)
    pv_kernel<<<dim3(Kc / BN, Tc / BM, Bc * Hc), blk>>>();

    // Stage 5: output projection (8192 x 512 x 4096) + bias
    out_kernel<<<dim3(Kc / BN, M0 / BM), blk>>>(Wu, bu, out);
}

// round 4
// speedup vs baseline: 2.6323x; 2.6323x over previous
#include <cuda_runtime.h>
#include <cuda_bf16.h>
#include <cstdint>

// ---------------------------------------------------------------------------
// Problem constants
// ---------------------------------------------------------------------------
#define Bc 4
#define Hc 8
#define Tc 2048
#define Kc 512
#define KH 4096
#define M0 8192
#define INV4 0.2102241038134287f   // 512^(-0.25)

// Element counts
#define NA  ((size_t)M0 * Kc)        // x            4.19M
#define NW  ((size_t)Kc * KH)        // weights      2.10M
#define NQ  ((size_t)Bc * Hc * Tc * Kc)  // q/k/v    33.6M
#define NS  ((size_t)Bc * Hc * Tc * Tc)  // scores   134.2M
#define NATT ((size_t)M0 * KH)       // att         33.6M

// ---------------------------------------------------------------------------
// Static device scratch (module-load allocated; no runtime allocation)
// ---------------------------------------------------------------------------
__device__ __align__(16) __nv_bfloat16 g_xh[NA],  g_xl[NA];
__device__ __align__(16) __nv_bfloat16 g_WqTh[NW], g_WqTl[NW];
__device__ __align__(16) __nv_bfloat16 g_WkTh[NW], g_WkTl[NW];
__device__ __align__(16) __nv_bfloat16 g_WvTh[NW], g_WvTl[NW];
__device__ __align__(16) __nv_bfloat16 g_WuTh[NW], g_WuTl[NW];
__device__ float g_q32[NQ], g_k32[NQ], g_v32[NQ];
__device__ __align__(16) __nv_bfloat16 g_qh[NQ], g_ql[NQ], g_kh[NQ], g_kl[NQ];
__device__ __align__(16) __nv_bfloat16 g_vTh[NQ], g_vTl[NQ];
__device__ float g_s32[NS];
__device__ __align__(16) __nv_bfloat16 g_ph[NS], g_pl[NS];
__device__ float g_att32[NATT];
__device__ __align__(16) __nv_bfloat16 g_atth[NATT], g_attl[NATT];

// ---------------------------------------------------------------------------
// PTX helpers
// ---------------------------------------------------------------------------
__device__ __forceinline__ void cpa16(const void* smemPtr, const void* gptr) {
    uint32_t s = (uint32_t)__cvta_generic_to_shared(smemPtr);
    asm volatile("cp.async.cg.shared.global [%0], [%1], 16;" :: "r"(s), "l"(gptr));
}

__device__ __forceinline__ void ldsm4(uint32_t* d, const __nv_bfloat16* p) {
    uint32_t a = (uint32_t)__cvta_generic_to_shared(p);
    asm volatile("ldmatrix.sync.aligned.m8n8.x4.shared.b16 {%0,%1,%2,%3}, [%4];"
                 : "=r"(d[0]), "=r"(d[1]), "=r"(d[2]), "=r"(d[3]) : "r"(a));
}

__device__ __forceinline__ void mma16816(float* c, const uint32_t* a, const uint32_t* b) {
    asm volatile(
        "mma.sync.aligned.m16n8k16.row.col.f32.bf16.bf16.f32 "
        "{%0,%1,%2,%3}, {%4,%5,%6,%7}, {%8,%9}, {%0,%1,%2,%3};"
        : "+f"(c[0]), "+f"(c[1]), "+f"(c[2]), "+f"(c[3])
        : "r"(a[0]), "r"(a[1]), "r"(a[2]), "r"(a[3]), "r"(b[0]), "r"(b[1]));
}

// Swizzled smem offset (bf16 elements) for tile row r, 8-elem chunk kc (0..3).
// Row = 32 bf16 = 64B = 4 chunks; swizzle kc ^ ((r>>1)&3) makes every
// 8-address ldmatrix / cp.async phase hit 8 distinct 16B bank slots.
__device__ __forceinline__ int sw_off(int r, int kc) {
    return r * 32 + ((kc ^ ((r >> 1) & 3)) << 3);
}

// ---------------------------------------------------------------------------
// Generic 3-pass split-bf16 MMA GEMM.
// C[z] (fp32) = A[z] * B[z]^T where A stored [M][Kdim], B stored [N][Kdim]
// (both k-contiguous), both as (hi, lo) bf16 pairs.
// CTA tile 128x128, BK=32, 8 warps of 32(M)x64(N), double-buffered cp.async.
// mode: 0 = C + z*strideCz + r*ldc + c   (+bias if non-null)
//       1 = qkv layout [b,h,t,k] from (r=b*2048+t, c=h*512+k)
//       2 = pv  layout [b,t,h*512+k] from (z=b*8+h, r=t, c=k)
// ---------------------------------------------------------------------------
__device__ __forceinline__ float* caddr(float* C, int mode, int ldc,
                                        size_t strideCz, int z, int r, int c) {
    if (mode == 0)
        return C + (size_t)z * strideCz + (size_t)r * ldc + c;
    if (mode == 1)
        return C + ((size_t)((r >> 11) * 8 + (c >> 9))) * ((size_t)Tc * Kc)
                 + (size_t)(r & (Tc - 1)) * Kc + (c & (Kc - 1));
    return C + ((size_t)(z >> 3) * Tc + r) * KH + (z & 7) * Kc + c;
}

__device__ __forceinline__ void load_tiles(
    __nv_bfloat16* s,
    const __nv_bfloat16* gAh, const __nv_bfloat16* gAl,
    const __nv_bfloat16* gBh, const __nv_bfloat16* gBl,
    int Kdim, int k0, int tid)
{
#pragma unroll
    for (int i = 0; i < 2; i++) {
        int c = tid + (i << 8);          // 0..511
        int r = c >> 2, kc = c & 3;
        int so = sw_off(r, kc);
        size_t go = (size_t)r * Kdim + k0 + (kc << 3);
        cpa16(s + so,         gAh + go);
        cpa16(s + 4096 + so,  gAl + go);
        cpa16(s + 8192 + so,  gBh + go);
        cpa16(s + 12288 + so, gBl + go);
    }
    asm volatile("cp.async.commit_group;" ::: "memory");
}

__device__ __forceinline__ void compute_tiles(
    const __nv_bfloat16* sb, float (&acc)[2][8][4],
    int m0, int n0, int lane)
{
    const __nv_bfloat16* sAh = sb;
    const __nv_bfloat16* sAl = sb + 4096;
    const __nv_bfloat16* sBh = sb + 8192;
    const __nv_bfloat16* sBl = sb + 12288;

    const int laneA_r = lane & 15;
    const int laneA_c = lane >> 4;
    const int laneB_r = (lane & 7) | ((lane >> 1) & 8);
    const int laneB_c = (lane >> 3) & 1;

#pragma unroll
    for (int ks8 = 0; ks8 < 4; ks8 += 2) {     // two k16 steps per BK32
        uint32_t aH[2][4], aL[2][4];
#pragma unroll
        for (int mt = 0; mt < 2; mt++) {
            int r = m0 + mt * 16 + laneA_r;
            int so = sw_off(r, ks8 + laneA_c);
            ldsm4(aH[mt], sAh + so);
            ldsm4(aL[mt], sAl + so);
        }
#pragma unroll
        for (int np = 0; np < 4; np++) {
            int r = n0 + np * 16 + laneB_r;
            int so = sw_off(r, ks8 + laneB_c);
            uint32_t bH[4], bL[4];
            ldsm4(bH, sBh + so);
            ldsm4(bL, sBl + so);
            // pass-major ordering: 4-wide independent chains per acc
#pragma unroll
            for (int mt = 0; mt < 2; mt++)
#pragma unroll
                for (int j = 0; j < 2; j++)
                    mma16816(acc[mt][np * 2 + j], aH[mt], bH + j * 2);
#pragma unroll
            for (int mt = 0; mt < 2; mt++)
#pragma unroll
                for (int j = 0; j < 2; j++)
                    mma16816(acc[mt][np * 2 + j], aH[mt], bL + j * 2);
#pragma unroll
            for (int mt = 0; mt < 2; mt++)
#pragma unroll
                for (int j = 0; j < 2; j++)
                    mma16816(acc[mt][np * 2 + j], aL[mt], bH + j * 2);
        }
    }
}

__global__ __launch_bounds__(256, 2)
void mma_gemm(const __nv_bfloat16* __restrict__ Ah, const __nv_bfloat16* __restrict__ Al,
              const __nv_bfloat16* __restrict__ Bh, const __nv_bfloat16* __restrict__ Bl,
              float* __restrict__ C, const float* __restrict__ bias,
              int Kdim, int ldc,
              size_t strideAz, size_t strideBz, size_t strideCz,
              int mode)
{
    extern __shared__ __nv_bfloat16 smem[];   // 2 bufs x 16384 bf16 = 64KB

    const int tid = threadIdx.x;
    const int lane = tid & 31, warp = tid >> 5;
    const int z = blockIdx.z;
    const int blockM = blockIdx.y * 128, blockN = blockIdx.x * 128;
    const int m0 = (warp >> 1) * 32, n0 = (warp & 1) * 64;

    const __nv_bfloat16* gAh = Ah + (size_t)z * strideAz + (size_t)blockM * Kdim;
    const __nv_bfloat16* gAl = Al + (size_t)z * strideAz + (size_t)blockM * Kdim;
    const __nv_bfloat16* gBh = Bh + (size_t)z * strideBz + (size_t)blockN * Kdim;
    const __nv_bfloat16* gBl = Bl + (size_t)z * strideBz + (size_t)blockN * Kdim;

    float acc[2][8][4];
#pragma unroll
    for (int a = 0; a < 2; a++)
#pragma unroll
        for (int b = 0; b < 8; b++)
#pragma unroll
            for (int c = 0; c < 4; c++) acc[a][b][c] = 0.f;

    const int nk = Kdim >> 5;
    load_tiles(smem, gAh, gAl, gBh, gBl, Kdim, 0, tid);

    for (int i = 0; i < nk; i++) {
        if (i + 1 < nk) {
            load_tiles(smem + ((i + 1) & 1) * 16384, gAh, gAl, gBh, gBl,
                       Kdim, (i + 1) << 5, tid);
            asm volatile("cp.async.wait_group 1;" ::: "memory");
        } else {
            asm volatile("cp.async.wait_group 0;" ::: "memory");
        }
        __syncthreads();
        compute_tiles(smem + (i & 1) * 16384, acc, m0, n0, lane);
        __syncthreads();
    }

    // Epilogue
#pragma unroll
    for (int mt = 0; mt < 2; mt++)
#pragma unroll
        for (int nt = 0; nt < 8; nt++) {
            int gr = blockM + m0 + mt * 16 + (lane >> 2);
            int gc = blockN + n0 + nt * 8 + ((lane & 3) << 1);
            float c0 = acc[mt][nt][0], c1 = acc[mt][nt][1];
            float c2 = acc[mt][nt][2], c3 = acc[mt][nt][3];
            if (bias) {
                float b0 = bias[gc], b1 = bias[gc + 1];
                c0 += b0; c1 += b1; c2 += b0; c3 += b1;
            }
            float* p0 = caddr(C, mode, ldc, strideCz, z, gr, gc);
            float* p1 = caddr(C, mode, ldc, strideCz, z, gr + 8, gc);
            p0[0] = c0; p0[1] = c1;
            p1[0] = c2; p1[1] = c3;
        }
}

// ---------------------------------------------------------------------------
// fp32 -> (hi, lo) bf16 split, elementwise (optional scale)
// ---------------------------------------------------------------------------
__global__ void split_kernel(const float* __restrict__ src,
                             __nv_bfloat16* __restrict__ hi,
                             __nv_bfloat16* __restrict__ lo,
                             float scale, int n4)
{
    int i = blockIdx.x * blockDim.x + threadIdx.x;
    if (i >= n4) return;
    float4 v = ((const float4*)src)[i];
    v.x *= scale; v.y *= scale; v.z *= scale; v.w *= scale;
    float f[4] = {v.x, v.y, v.z, v.w};
    __nv_bfloat16 h[4], l[4];
#pragma unroll
    for (int j = 0; j < 4; j++) {
        h[j] = __float2bfloat16(f[j]);
        l[j] = __float2bfloat16(f[j] - __bfloat162float(h[j]));
    }
    ((__nv_bfloat162*)hi)[2 * i]     = __nv_bfloat162(h[0], h[1]);
    ((__nv_bfloat162*)hi)[2 * i + 1] = __nv_bfloat162(h[2], h[3]);
    ((__nv_bfloat162*)lo)[2 * i]     = __nv_bfloat162(l[0], l[1]);
    ((__nv_bfloat162*)lo)[2 * i + 1] = __nv_bfloat162(l[2], l[3]);
}

// ---------------------------------------------------------------------------
// fp32 [R][C] -> transposed (hi, lo) bf16 [C][R], batched over z
// ---------------------------------------------------------------------------
__global__ void tsplit_kernel(const float* __restrict__ src,
                              __nv_bfloat16* __restrict__ hi,
                              __nv_bfloat16* __restrict__ lo,
                              int R, int C)
{
    __shared__ float t[32][33];
    size_t zoff = (size_t)blockIdx.z * R * C;
    const float* s = src + zoff;
    __nv_bfloat16* ho = hi + zoff;
    __nv_bfloat16* lor = lo + zoff;
    int c0 = blockIdx.x * 32, r0 = blockIdx.y * 32;

#pragma unroll
    for (int i = 0; i < 4; i++) {
        int r = r0 + threadIdx.y + i * 8;
        t[threadIdx.y + i * 8][threadIdx.x] = s[(size_t)r * C + c0 + threadIdx.x];
    }
    __syncthreads();
#pragma unroll
    for (int i = 0; i < 4; i++) {
        int cc = c0 + threadIdx.y + i * 8;   // dst row
        int rr = r0 + threadIdx.x;           // dst col
        float v = t[threadIdx.x][threadIdx.y + i * 8];
        __nv_bfloat16 h = __float2bfloat16(v);
        ho[(size_t)cc * R + rr] = h;
        lor[(size_t)cc * R + rr] = __float2bfloat16(v - __bfloat162float(h));
    }
}

// ---------------------------------------------------------------------------
// Row softmax (row length 2048) with (hi, lo) bf16 output
// ---------------------------------------------------------------------------
__global__ void softmax_split_kernel(const float* __restrict__ s,
                                     __nv_bfloat16* __restrict__ ph,
                                     __nv_bfloat16* __restrict__ pl)
{
    __shared__ float red[8];
    const size_t base = (size_t)blockIdx.x * Tc;
    const float* p = s + base;
    const int tid = threadIdx.x;

    float v[8];
    *(float4*)&v[0] = *(const float4*)(p + tid * 8);
    *(float4*)&v[4] = *(const float4*)(p + tid * 8 + 4);

    float mx = v[0];
#pragma unroll
    for (int i = 1; i < 8; i++) mx = fmaxf(mx, v[i]);
#pragma unroll
    for (int o = 16; o > 0; o >>= 1)
        mx = fmaxf(mx, __shfl_xor_sync(0xffffffffu, mx, o));
    if ((tid & 31) == 0) red[tid >> 5] = mx;
    __syncthreads();
    mx = red[0];
#pragma unroll
    for (int i = 1; i < 8; i++) mx = fmaxf(mx, red[i]);

    float sum = 0.f;
#pragma unroll
    for (int i = 0; i < 8; i++) { v[i] = __expf(v[i] - mx); sum += v[i]; }
#pragma unroll
    for (int o = 16; o > 0; o >>= 1)
        sum += __shfl_xor_sync(0xffffffffu, sum, o);
    __syncthreads();
    if ((tid & 31) == 0) red[tid >> 5] = sum;
    __syncthreads();
    sum = 0.f;
#pragma unroll
    for (int i = 0; i < 8; i++) sum += red[i];
    const float inv = 1.f / sum;

    __nv_bfloat16 h[8], l[8];
#pragma unroll
    for (int i = 0; i < 8; i++) {
        float q = v[i] * inv;
        h[i] = __float2bfloat16(q);
        l[i] = __float2bfloat16(q - __bfloat162float(h[i]));
    }
#pragma unroll
    for (int i = 0; i < 4; i++) {
        ((__nv_bfloat162*)(ph + base))[tid * 4 + i] = __nv_bfloat162(h[2*i], h[2*i+1]);
        ((__nv_bfloat162*)(pl + base))[tid * 4 + i] = __nv_bfloat162(l[2*i], l[2*i+1]);
    }
}

// ---------------------------------------------------------------------------
// kernel_launch
// Inputs: x, Wq, Wk, Wv, Wu, bu. Output: float [8192, 512].
// ---------------------------------------------------------------------------
#define GETSYM(var, sym) \
    { void* _p; cudaGetSymbolAddress(&_p, sym); var = decltype(var)(_p); }

extern "C" void kernel_launch(void* const* d_in, const int* in_sizes, int n_in,
                              void* d_out, int out_size)
{
    const float* x  = (const float*)d_in[0];
    const float* Wq = (const float*)d_in[1];
    const float* Wk = (const float*)d_in[2];
    const float* Wv = (const float*)d_in[3];
    const float* Wu = (const float*)d_in[4];
    const float* bu = (const float*)d_in[5];
    float* out = (float*)d_out;
    (void)in_sizes; (void)n_in; (void)out_size;

    cudaFuncSetAttribute(mma_gemm, cudaFuncAttributeMaxDynamicSharedMemorySize, 65536);

    __nv_bfloat16 *xh, *xl, *WqTh, *WqTl, *WkTh, *WkTl, *WvTh, *WvTl, *WuTh, *WuTl;
    __nv_bfloat16 *qh, *ql, *kh, *kl, *vTh, *vTl, *ph, *pl, *atth, *attl;
    float *q32, *k32, *v32, *s32, *att32;
    GETSYM(xh, g_xh); GETSYM(xl, g_xl);
    GETSYM(WqTh, g_WqTh); GETSYM(WqTl, g_WqTl);
    GETSYM(WkTh, g_WkTh); GETSYM(WkTl, g_WkTl);
    GETSYM(WvTh, g_WvTh); GETSYM(WvTl, g_WvTl);
    GETSYM(WuTh, g_WuTh); GETSYM(WuTl, g_WuTl);
    GETSYM(q32, g_q32); GETSYM(k32, g_k32); GETSYM(v32, g_v32);
    GETSYM(qh, g_qh); GETSYM(ql, g_ql); GETSYM(kh, g_kh); GETSYM(kl, g_kl);
    GETSYM(vTh, g_vTh); GETSYM(vTl, g_vTl);
    GETSYM(s32, g_s32); GETSYM(ph, g_ph); GETSYM(pl, g_pl);
    GETSYM(att32, g_att32); GETSYM(atth, g_atth); GETSYM(attl, g_attl);

    const dim3 tb(32, 8);

    // --- input conversions ---
    split_kernel<<<(int)(NA / 4 / 256), 256>>>(x, xh, xl, 1.f, (int)(NA / 4));
    tsplit_kernel<<<dim3(KH / 32, Kc / 32, 1), tb>>>(Wq, WqTh, WqTl, Kc, KH);
    tsplit_kernel<<<dim3(KH / 32, Kc / 32, 1), tb>>>(Wk, WkTh, WkTl, Kc, KH);
    tsplit_kernel<<<dim3(KH / 32, Kc / 32, 1), tb>>>(Wv, WvTh, WvTl, Kc, KH);
    tsplit_kernel<<<dim3(Kc / 32, KH / 32, 1), tb>>>(Wu, WuTh, WuTl, KH, Kc);

    // --- stage 1: QKV projections (M=8192, N=4096, K=512) ---
    dim3 gq(KH / 128, M0 / 128, 1);
    mma_gemm<<<gq, 256, 65536>>>(xh, xl, WqTh, WqTl, q32, nullptr, Kc, 0, 0, 0, 0, 1);
    mma_gemm<<<gq, 256, 65536>>>(xh, xl, WkTh, WkTl, k32, nullptr, Kc, 0, 0, 0, 0, 1);
    mma_gemm<<<gq, 256, 65536>>>(xh, xl, WvTh, WvTl, v32, nullptr, Kc, 0, 0, 0, 0, 1);

    // --- convert q/k (scaled) and v (transposed per head) ---
    split_kernel<<<(int)(NQ / 4 / 256), 256>>>(q32, qh, ql, INV4, (int)(NQ / 4));
    split_kernel<<<(int)(NQ / 4 / 256), 256>>>(k32, kh, kl, INV4, (int)(NQ / 4));
    tsplit_kernel<<<dim3(Kc / 32, Tc / 32, Bc * Hc), tb>>>(v32, vTh, vTl, Tc, Kc);

    // --- stage 2: scores (M=N=2048, K=512, z=32) ---
    mma_gemm<<<dim3(Tc / 128, Tc / 128, Bc * Hc), 256, 65536>>>(
        qh, ql, kh, kl, s32, nullptr, Kc, Tc,
        (size_t)Tc * Kc, (size_t)Tc * Kc, (size_t)Tc * Tc, 0);

    // --- stage 3: softmax -> split probs ---
    softmax_split_kernel<<<Bc * Hc * Tc, 256>>>(s32, ph, pl);

    // --- stage 4: PV (M=2048, N=512, K=2048, z=32) ---
    mma_gemm<<<dim3(Kc / 128, Tc / 128, Bc * Hc), 256, 65536>>>(
        ph, pl, vTh, vTl, att32, nullptr, Tc, 0,
        (size_t)Tc * Tc, (size_t)Kc * Tc, 0, 2);

    // --- convert att ---
    split_kernel<<<(int)(NATT / 4 / 256), 256>>>(att32, atth, attl, 1.f, (int)(NATT / 4));

    // --- stage 5: output projection + bias (M=8192, N=512, K=4096) ---
    mma_gemm<<<dim3(Kc / 128, M0 / 128, 1), 256, 65536>>>(
        atth, attl, WuTh, WuTl, out, bu, KH, Kc, 0, 0, 0, 0);
}